// round 7
// baseline (speedup 1.0000x reference)
#include <cuda_runtime.h>
#include <cuda_bf16.h>
#include <cstdint>

// Problem constants
#define BB 2048   // batch
#define BP 2058   // padded batch (147 CTAs * 14 rows)
#define TT 64     // timesteps
#define HH 64     // LSTM hidden
#define GG 256    // 4*H gates
#define NL 8      // LSTM layers
#define BT 14     // batch rows per CTA (recurrence)
#define NCTA 147
#define NS 4      // K splits (both kernels)
#define RT 16     // rows per CTA (xg kernel)

// Ping-pong inter-layer buffers, layout [T, BP, H] (layer0 input uses [T, BP, 16])
__device__ float g_bufA[(size_t)TT * BP * HH + 256];
__device__ float g_bufB[(size_t)TT * BP * HH + 256];
// Precomputed input-gate buffer xg = in @ w_ih^T + (b_ih + b_hh), [T, BP, 256]
__device__ float g_xg[(size_t)TT * BP * GG + 256];

__device__ __forceinline__ float* bufptr(int s) { return s ? g_bufB : g_bufA; }

__device__ __forceinline__ float sigm(float x) {
    return __fdividef(1.0f, 1.0f + __expf(-x));
}
__device__ __forceinline__ float tanh_(float x) {
    return __fdividef(2.0f, 1.0f + __expf(-2.0f * x)) - 1.0f;
}

// ---- packed f32x2 helpers (Blackwell FFMA2; PTX-only) ----
__device__ __forceinline__ void ffma2(uint64_t& d, uint64_t a, uint64_t b) {
    asm("fma.rn.f32x2 %0, %1, %2, %0;" : "+l"(d) : "l"(a), "l"(b));
}
__device__ __forceinline__ uint64_t pack2(float lo, float hi) {
    uint64_t r;
    asm("mov.b64 %0, {%1, %2};" : "=l"(r) : "f"(lo), "f"(hi));
    return r;
}
__device__ __forceinline__ float hsum2(uint64_t v) {
    float lo, hi;
    asm("mov.b64 {%0, %1}, %2;" : "=f"(lo), "=f"(hi) : "l"(v));
    return lo + hi;
}

// ---------------------------------------------------------------------------
// Input MLP: x[B,T,2] -> relu(x@w1^T+b1)@w2^T+b2 -> g_bufA as [T,BP,16]
// ---------------------------------------------------------------------------
__global__ void mlp_in_kernel(const float* __restrict__ x,
                              const float* __restrict__ w1, const float* __restrict__ b1,
                              const float* __restrict__ w2, const float* __restrict__ b2)
{
    __shared__ float s_w1[16][2], s_b1[16], s_w2[16][16], s_b2[16];
    int tid = threadIdx.x;
    if (tid < 32) { s_w1[tid / 2][tid % 2] = w1[tid]; }
    if (tid < 16) { s_b1[tid] = b1[tid]; s_b2[tid] = b2[tid]; }
    if (tid >= 32 && tid < 32 + 256) {
        int i = tid - 32;
        s_w2[i / 16][i % 16] = w2[i];
    }
    __syncthreads();

    int idx = blockIdx.x * blockDim.x + tid;      // 0 .. B*T-1, idx = b*T + t
    int b = idx / TT;
    int t = idx % TT;
    float x0 = x[(size_t)idx * 2 + 0];
    float x1 = x[(size_t)idx * 2 + 1];

    float h1[16];
#pragma unroll
    for (int j = 0; j < 16; j++) {
        float v = fmaf(s_w1[j][0], x0, fmaf(s_w1[j][1], x1, s_b1[j]));
        h1[j] = fmaxf(v, 0.0f);
    }
    float* dst = g_bufA + (size_t)t * BP * 16 + (size_t)b * 16;
#pragma unroll
    for (int j = 0; j < 16; j++) {
        float o = s_b2[j];
#pragma unroll
        for (int k = 0; k < 16; k++) o = fmaf(s_w2[j][k], h1[k], o);
        dst[j] = o;
    }
}

// ---------------------------------------------------------------------------
// xg precompute GEMM: g_xg[row, j] = in[row,:] @ w_ih[j,:] + (b_ih[j]+b_hh[j])
// 256 threads = 64 col-quads (cols g, g+64, g+128, g+192) x 4 K-splits.
// RT=16 rows per CTA in 8 chunks of 2 (acc = 16 u64 -> no spill).
// Each broadcast LDS.128 feeds 8 FFMA2.
// ---------------------------------------------------------------------------
template <int I>
__global__ void __launch_bounds__(256, 2)
xg_kernel(int insel,
          const float* __restrict__ w_ih,
          const float* __restrict__ b_ih, const float* __restrict__ b_hh)
{
    constexpr int KH = I / NS;            // 16 (I=64), 4 (I=16)

    extern __shared__ float smem[];
    float* s_in = smem;                   // [RT][I]
    float* s_gp = s_in + RT * I;          // [16][RT][64]

    const float* in = bufptr(insel);
    const int tid = threadIdx.x;
    const int g   = tid & 63;             // col-quad
    const int q   = tid >> 6;             // K split
    const size_t row0 = (size_t)blockIdx.x * RT;

    // weights for 4 cols x KH ks, as even/odd-k u64 pairs
    uint64_t w[4][KH / 2];
#pragma unroll
    for (int c = 0; c < 4; c++) {
        const int j = g + c * 64;
        const uint64_t* wp = reinterpret_cast<const uint64_t*>(w_ih) + (size_t)j * (I / 2) + q * (KH / 2);
#pragma unroll
        for (int i = 0; i < KH / 2; i++) w[c][i] = wp[i];
    }
    uint64_t bias[4];
#pragma unroll
    for (int c = 0; c < 4; c++)
        bias[c] = (q == 0) ? pack2(b_ih[g + c * 64] + b_hh[g + c * 64], 0.0f) : 0ull;

    // stage input tile (contiguous RT*I floats)
    {
        const float4* src = reinterpret_cast<const float4*>(in + row0 * I);
        float4* dst = reinterpret_cast<float4*>(s_in);
        for (int i = tid; i < RT * I / 4; i += 256) dst[i] = src[i];
    }
    __syncthreads();

    // 8 chunks of 2 rows (acc = 8 u64 live -> fits registers)
#pragma unroll
    for (int ch = 0; ch < 8; ch++) {
        const int rs = ch * 2;
        uint64_t acc[4][2];               // [c][r]
#pragma unroll
        for (int c = 0; c < 4; c++)
#pragma unroll
            for (int r = 0; r < 2; r++) acc[c][r] = bias[c];

#pragma unroll
        for (int kk = 0; kk < KH; kk += 4) {
#pragma unroll
            for (int r = 0; r < 2; r++) {
                ulonglong2 v = *reinterpret_cast<const ulonglong2*>(
                    s_in + (size_t)(rs + r) * I + q * KH + kk);   // LDS.128 broadcast
#pragma unroll
                for (int c = 0; c < 4; c++) {
                    ffma2(acc[c][r], v.x, w[c][kk / 2]);
                    ffma2(acc[c][r], v.y, w[c][kk / 2 + 1]);
                }
            }
        }
#pragma unroll
        for (int c = 0; c < 4; c++)
#pragma unroll
            for (int r = 0; r < 2; r++)
                s_gp[((c * NS + q) * RT + rs + r) * 64 + g] = hsum2(acc[c][r]);
    }
    __syncthreads();

    // fold partials, store: 16 outputs per thread (column j = tid, rows 0..15)
#pragma unroll
    for (int o = 0; o < RT; o++) {
        int r = o;
        int j = tid;
        int c = j >> 6, u = j & 63;
        float s = 0.f;
#pragma unroll
        for (int qq = 0; qq < NS; qq++)
            s += s_gp[((c * NS + qq) * RT + r) * 64 + u];
        g_xg[(row0 + r) * GG + j] = s;
    }
}

// ---------------------------------------------------------------------------
// Recurrence: gates = xg[t] + h @ w_hh^T, cell update. 512 threads =
// 64 unit-quads (cols u,u+64,u+128,u+192 = 4 gates of unit u) x 4 K-splits
// x 2 row-halves (7 rows each, chunks 2+2+2+1; acc = 16 u64 -> no spill).
// Partials s_gp[gate*4+q][BT][64]. xg(t+1) prefetched LDG->regs->STS.
// ---------------------------------------------------------------------------
__global__ void __launch_bounds__(512, 1)
lstm_rec_kernel(int outsel, const float* __restrict__ w_hh)
{
    constexpr int KH = HH / NS;           // 16

    extern __shared__ float smem[];
    float* s_h  = smem;                   // [BT][HH]
    float* s_c  = s_h + BT * HH;          // [BT][HH]
    float* s_xg = s_c + BT * HH;          // [2][BT][GG]
    float* s_gp = s_xg + 2 * BT * GG;     // [16][BT][64]

    float* out = bufptr(outsel);
    const int tid = threadIdx.x;
    const int g   = tid & 63;             // unit-quad
    const int q   = (tid >> 6) & 3;       // K split
    const int rh  = tid >> 8;             // row half
    const int b0  = blockIdx.x * BT;

    // weights: 4 gates of unit g, K window [q*16, q*16+16)
    uint64_t w[4][KH / 2];
#pragma unroll
    for (int c = 0; c < 4; c++) {
        const int j = g + c * 64;
        const uint64_t* wp = reinterpret_cast<const uint64_t*>(w_hh) + (size_t)j * (HH / 2) + q * (KH / 2);
#pragma unroll
        for (int i = 0; i < KH / 2; i++) w[c][i] = wp[i];
    }

    // h0 = c0 = 0
    for (int i = tid; i < BT * HH; i += 512) { s_h[i] = 0.0f; s_c[i] = 0.0f; }
    // stage xg(0)
    {
        const float4* src = reinterpret_cast<const float4*>(g_xg + (size_t)b0 * GG);
        float4* dst = reinterpret_cast<float4*>(s_xg);
        for (int i = tid; i < BT * GG / 4; i += 512) dst[i] = src[i];
    }
    __syncthreads();

    const int rbase = rh * 7;             // this thread's 7 rows

    for (int t = 0; t < TT; t++) {
        // prefetch xg(t+1) into regs (hidden under mainloop)
        float4 pf0, pf1;
        const bool do_pf = (t + 1 < TT);
        if (do_pf) {
            const float4* src = reinterpret_cast<const float4*>(
                g_xg + ((size_t)(t + 1) * BP + b0) * GG);
            pf0 = src[tid];
            if (tid < BT * GG / 4 - 512) pf1 = src[tid + 512];
        }

        // --- gate partials: 4 chunks of rows (2,2,2,1) within my half ---
#pragma unroll
        for (int ch = 0; ch < 4; ch++) {
            const int rs = rbase + ch * 2;
            const int rn = (ch == 3) ? 1 : 2;
            uint64_t acc[4][2];           // [c][r]
#pragma unroll
            for (int c = 0; c < 4; c++)
#pragma unroll
                for (int r = 0; r < 2; r++) acc[c][r] = 0ull;

#pragma unroll
            for (int kk = 0; kk < KH; kk += 4) {
#pragma unroll
                for (int r = 0; r < 2; r++) {
                    if (r < rn) {
                        ulonglong2 v = *reinterpret_cast<const ulonglong2*>(
                            s_h + (size_t)(rs + r) * HH + q * KH + kk);   // LDS.128 broadcast
#pragma unroll
                        for (int c = 0; c < 4; c++) {
                            ffma2(acc[c][r], v.x, w[c][kk / 2]);
                            ffma2(acc[c][r], v.y, w[c][kk / 2 + 1]);
                        }
                    }
                }
            }
#pragma unroll
            for (int c = 0; c < 4; c++)
#pragma unroll
                for (int r = 0; r < 2; r++)
                    if (r < rn)
                        s_gp[((c * NS + q) * BT + rs + r) * 64 + g] = hsum2(acc[c][r]);
        }

        // commit prefetched xg(t+1)
        if (do_pf) {
            float4* dst = reinterpret_cast<float4*>(s_xg + ((t + 1) & 1) * BT * GG);
            dst[tid] = pf0;
            if (tid < BT * GG / 4 - 512) dst[tid + 512] = pf1;
        }
        __syncthreads();

        // --- elementwise: BT*64 = 896 units over 512 threads ---
        const float* xgb = s_xg + (t & 1) * BT * GG;
#pragma unroll
        for (int pp = 0; pp < 2; pp++) {
            int ul = pp * 512 + tid;
            if (ul < BT * HH) {
                int r = ul >> 6;
                int u = ul & 63;
                float gi = xgb[r * GG + u];
                float gf = xgb[r * GG + 64 + u];
                float gg = xgb[r * GG + 128 + u];
                float go = xgb[r * GG + 192 + u];
#pragma unroll
                for (int qq = 0; qq < NS; qq++) {
                    gi += s_gp[((0 * NS + qq) * BT + r) * 64 + u];
                    gf += s_gp[((1 * NS + qq) * BT + r) * 64 + u];
                    gg += s_gp[((2 * NS + qq) * BT + r) * 64 + u];
                    go += s_gp[((3 * NS + qq) * BT + r) * 64 + u];
                }
                float iv = sigm(gi);
                float fv = sigm(gf);
                float gv = tanh_(gg);
                float ov = sigm(go);
                float c  = fmaf(fv, s_c[r * HH + u], iv * gv);
                float h  = ov * tanh_(c);
                s_c[r * HH + u] = c;
                s_h[r * HH + u] = h;
                out[(size_t)t * BP * HH + (size_t)(b0 + r) * HH + u] = h;
            }
        }
        __syncthreads();   // protects s_h / s_gp / s_xg for next step
    }
}

// ---------------------------------------------------------------------------
// Output MLP: h[T,BP,64] -> relu(h@wo1^T+bo1)@wo2^T+bo2 -> out[B,T,4]
// ---------------------------------------------------------------------------
__global__ void mlp_out_kernel(int insel,
                               const float* __restrict__ wo1, const float* __restrict__ bo1,
                               const float* __restrict__ wo2, const float* __restrict__ bo2,
                               float* __restrict__ outp)
{
    __shared__ float s_w1[32][64];
    __shared__ float s_b1[32];
    __shared__ float s_w2[4][32];
    __shared__ float s_b2[4];
    int tid = threadIdx.x;
    for (int i = tid; i < 32 * 64; i += 256) s_w1[i / 64][i % 64] = wo1[i];
    if (tid < 32) s_b1[tid] = bo1[tid];
    if (tid < 128) s_w2[tid / 32][tid % 32] = wo2[tid];
    if (tid < 4) s_b2[tid] = bo2[tid];
    __syncthreads();

    const float* in = bufptr(insel);
    int idx = blockIdx.x * blockDim.x + tid;   // idx = t*B + b (coalesced h reads)
    int t = idx / BB;
    int b = idx % BB;

    float h[64];
    const float4* src = reinterpret_cast<const float4*>(in + ((size_t)t * BP + b) * HH);
#pragma unroll
    for (int i = 0; i < 16; i++) {
        float4 v = src[i];
        h[4 * i + 0] = v.x; h[4 * i + 1] = v.y; h[4 * i + 2] = v.z; h[4 * i + 3] = v.w;
    }

    float h2[32];
#pragma unroll
    for (int j = 0; j < 32; j++) {
        float o = s_b1[j];
#pragma unroll
        for (int k = 0; k < 64; k++) o = fmaf(s_w1[j][k], h[k], o);
        h2[j] = fmaxf(o, 0.0f);
    }
    float* dst = outp + ((size_t)b * TT + t) * 4;
#pragma unroll
    for (int j = 0; j < 4; j++) {
        float o = s_b2[j];
#pragma unroll
        for (int k = 0; k < 32; k++) o = fmaf(s_w2[j][k], h2[k], o);
        dst[j] = o;
    }
}

// ---------------------------------------------------------------------------
extern "C" void kernel_launch(void* const* d_in, const int* in_sizes, int n_in,
                              void* d_out, int out_size)
{
    const float* x     = (const float*)d_in[0];
    const float* w1    = (const float*)d_in[1];
    const float* b1    = (const float*)d_in[2];
    const float* w2    = (const float*)d_in[3];
    const float* b2    = (const float*)d_in[4];
    const float* w_ih0 = (const float*)d_in[5];
    const float* w_hh0 = (const float*)d_in[6];
    const float* b_ih0 = (const float*)d_in[7];
    const float* b_hh0 = (const float*)d_in[8];
    const float* w_ih  = (const float*)d_in[9];   // (7, 256, 64)
    const float* w_hh  = (const float*)d_in[10];  // (7, 256, 64)
    const float* b_ih  = (const float*)d_in[11];  // (7, 256)
    const float* b_hh  = (const float*)d_in[12];  // (7, 256)
    const float* wo1   = (const float*)d_in[13];
    const float* bo1   = (const float*)d_in[14];
    const float* wo2   = (const float*)d_in[15];
    const float* bo2   = (const float*)d_in[16];
    float* outp = (float*)d_out;

    const int smem_rec  = (2 * BT * HH + 2 * BT * GG + 16 * BT * 64) * 4;     // 93184 B
    const int smem_xg64 = (RT * 64 + 16 * RT * 64) * 4;                        // 69632 B
    const int smem_xg16 = (RT * 16 + 16 * RT * 64) * 4;                        // 66560 B
    cudaFuncSetAttribute(lstm_rec_kernel, cudaFuncAttributeMaxDynamicSharedMemorySize, smem_rec);
    cudaFuncSetAttribute(xg_kernel<64>, cudaFuncAttributeMaxDynamicSharedMemorySize, smem_xg64);
    cudaFuncSetAttribute(xg_kernel<16>, cudaFuncAttributeMaxDynamicSharedMemorySize, smem_xg16);

    const int nelem = BB * TT;               // 131072
    const int nrow  = TT * BP;               // 131712 (multiple of 16)

    mlp_in_kernel<<<nelem / 256, 256>>>(x, w1, b1, w2, b2);

    // layer 0: A(stride16) --xg--> rec --> B
    xg_kernel<16><<<nrow / RT, 256, smem_xg16>>>(0, w_ih0, b_ih0, b_hh0);
    lstm_rec_kernel<<<NCTA, 512, smem_rec>>>(1, w_hh0);

    // layers 1..7: ping-pong B->A->B->...
    int cur = 1;
    for (int l = 0; l < NL - 1; l++) {
        int nxt = cur ^ 1;
        xg_kernel<64><<<nrow / RT, 256, smem_xg64>>>(cur, w_ih + (size_t)l * GG * HH,
                                                     b_ih + (size_t)l * GG, b_hh + (size_t)l * GG);
        lstm_rec_kernel<<<NCTA, 512, smem_rec>>>(nxt, w_hh + (size_t)l * GG * HH);
        cur = nxt;
    }

    mlp_out_kernel<<<nelem / 256, 256>>>(cur, wo1, bo1, wo2, bo2, outp);
}

// round 8
// speedup vs baseline: 1.8954x; 1.8954x over previous
#include <cuda_runtime.h>
#include <cuda_bf16.h>
#include <cstdint>

// Problem constants
#define BB 2048   // batch
#define BP 2058   // padded batch (147 CTAs * 14 rows)
#define TT 64     // timesteps
#define HH 64     // LSTM hidden
#define GG 256    // 4*H gates
#define NL 8      // LSTM layers
#define BT 14     // batch rows per CTA
#define NCTA 147

// Ping-pong inter-layer buffers, layout [T, BP, 64] (all layers 64-wide; layer0
// input uses cols 0-15, cols 16-63 zeroed)
__device__ float g_bufA[(size_t)TT * BP * HH + 256];
__device__ float g_bufB[(size_t)TT * BP * HH + 256];

__device__ __forceinline__ float* bufptr(int s) { return s ? g_bufB : g_bufA; }

__device__ __forceinline__ float sigm(float x) {
    return __fdividef(1.0f, 1.0f + __expf(-x));
}
__device__ __forceinline__ float tanh_(float x) {
    return __fdividef(2.0f, 1.0f + __expf(-2.0f * x)) - 1.0f;
}

// ---- packed f32x2 helpers (Blackwell FFMA2; PTX-only) ----
__device__ __forceinline__ void ffma2(uint64_t& d, uint64_t a, uint64_t b) {
    asm("fma.rn.f32x2 %0, %1, %2, %0;" : "+l"(d) : "l"(a), "l"(b));
}
__device__ __forceinline__ uint64_t pack2(float lo, float hi) {
    uint64_t r;
    asm("mov.b64 %0, {%1, %2};" : "=l"(r) : "f"(lo), "f"(hi));
    return r;
}
__device__ __forceinline__ float hsum2(uint64_t v) {
    float lo, hi;
    asm("mov.b64 {%0, %1}, %2;" : "=f"(lo), "=f"(hi) : "l"(v));
    return lo + hi;
}

// ---------------------------------------------------------------------------
// Input MLP: x[B,T,2] -> relu(x@w1^T+b1)@w2^T+b2 -> g_bufA[T,BP,64] (cols 0-15,
// cols 16-63 zeroed so layer 0 can run the uniform 64-wide LSTM kernel)
// ---------------------------------------------------------------------------
__global__ void mlp_in_kernel(const float* __restrict__ x,
                              const float* __restrict__ w1, const float* __restrict__ b1,
                              const float* __restrict__ w2, const float* __restrict__ b2)
{
    __shared__ float s_w1[16][2], s_b1[16], s_w2[16][16], s_b2[16];
    int tid = threadIdx.x;
    if (tid < 32) { s_w1[tid / 2][tid % 2] = w1[tid]; }
    if (tid < 16) { s_b1[tid] = b1[tid]; s_b2[tid] = b2[tid]; }
    if (tid >= 32 && tid < 32 + 256) {
        int i = tid - 32;
        s_w2[i / 16][i % 16] = w2[i];
    }
    __syncthreads();

    int idx = blockIdx.x * blockDim.x + tid;      // 0 .. B*T-1, idx = b*T + t
    int b = idx / TT;
    int t = idx % TT;
    float x0 = x[(size_t)idx * 2 + 0];
    float x1 = x[(size_t)idx * 2 + 1];

    float h1[16];
#pragma unroll
    for (int j = 0; j < 16; j++) {
        float v = fmaf(s_w1[j][0], x0, fmaf(s_w1[j][1], x1, s_b1[j]));
        h1[j] = fmaxf(v, 0.0f);
    }
    float* dst = g_bufA + ((size_t)t * BP + b) * 64;
#pragma unroll
    for (int j = 0; j < 16; j++) {
        float o = s_b2[j];
#pragma unroll
        for (int k = 0; k < 16; k++) o = fmaf(s_w2[j][k], h1[k], o);
        dst[j] = o;
    }
#pragma unroll
    for (int j = 16; j < 64; j++) dst[j] = 0.0f;
}

// ---------------------------------------------------------------------------
// Fused LSTM layer. 512 threads = 128 col-pairs (jA=p, jB=p+128) x 4 K-splits.
// K = concat(x[64], h[64]); q=0,1 own x ks [q*32,+32); q=2,3 own h ks.
// Weights 2 cols x 32 ks as 32 u64 pairs. Rows processed in chunks of <=4
// (acc[2][4] u64 -> no spill). Per step, 3-phase pipeline:
//   [ML rows0-7] bar [ML rows8-13 || EW rows0-7] bar [EW rows8-13 || x-commit] bar
// Partials in s_gp[plane=gate*4+q][BT][64] (conflict-free STS/LDS).
// x(t+1) prefetched LDG->regs during ML, committed to the other s_x buffer.
// ---------------------------------------------------------------------------
template <int IR>
__global__ void __launch_bounds__(512, 1)
lstm_fused(int insel, int outsel,
           const float* __restrict__ w_ih, const float* __restrict__ w_hh,
           const float* __restrict__ b_ih, const float* __restrict__ b_hh)
{
    extern __shared__ float smem[];
    float* s_x  = smem;                 // [2][BT][64]
    float* s_h  = s_x + 2 * BT * 64;    // [BT][64]
    float* s_c  = s_h + BT * 64;        // [BT][64]
    float* s_gp = s_c + BT * 64;        // [16][BT][64]  plane = gate*4+q

    const float* in  = bufptr(insel);
    float*       out = bufptr(outsel);
    const int tid = threadIdx.x;
    const int p   = tid & 127;          // column pair
    const int q   = tid >> 7;           // K split 0..3
    const int b0  = blockIdx.x * BT;
    const int glo = p >> 6;             // gate of jA: 0=i, 1=f
    const int u   = p & 63;             // unit

    // weights: c=0 -> col jA=p (gate glo), c=1 -> col jB=p+128 (gate 2+glo)
    uint64_t w[2][16];
#pragma unroll
    for (int c = 0; c < 2; c++) {
        const int j = p + c * 128;
#pragma unroll
        for (int kk = 0; kk < 32; kk += 2) {
            float a, b;
            if (q < 2) {
                int k = q * 32 + kk;
                a = (k     < IR) ? w_ih[(size_t)j * IR + k]     : 0.0f;
                b = (k + 1 < IR) ? w_ih[(size_t)j * IR + k + 1] : 0.0f;
            } else {
                int k = (q - 2) * 32 + kk;
                a = w_hh[(size_t)j * 64 + k];
                b = w_hh[(size_t)j * 64 + k + 1];
            }
            w[c][kk / 2] = pack2(a, b);
        }
    }
    uint64_t bias[2];
#pragma unroll
    for (int c = 0; c < 2; c++) {
        const int j = p + c * 128;
        bias[c] = (q == 0) ? pack2(b_ih[j] + b_hh[j], 0.0f) : 0ull;
    }

    // h0 = c0 = 0; stage x(0)
    for (int i = tid; i < BT * 64; i += 512) { s_h[i] = 0.0f; s_c[i] = 0.0f; }
    if (tid < BT * 16) {
        ((float4*)s_x)[tid] = ((const float4*)(in + (size_t)b0 * 64))[tid];
    }
    __syncthreads();

    for (int t = 0; t < TT; t++) {
        const int cur = t & 1, nxt = cur ^ 1;
        const float* ap = (q < 2) ? (s_x + cur * BT * 64 + q * 32)
                                  : (s_h + (q - 2) * 32);

        // prefetch x(t+1) into regs (hidden under mainloop)
        float4 pf;
        const bool do_pf = (t + 1 < TT) && (tid < BT * 16);
        if (do_pf)
            pf = ((const float4*)(in + ((size_t)(t + 1) * BP + b0) * 64))[tid];

        // ---- phase 1: ML rows 0..7 (2 chunks of 4) ----
#pragma unroll
        for (int ch = 0; ch < 2; ch++) {
            const int rs = ch * 4;
            uint64_t acc[2][4];
#pragma unroll
            for (int c = 0; c < 2; c++)
#pragma unroll
                for (int r = 0; r < 4; r++) acc[c][r] = bias[c];
#pragma unroll
            for (int kk = 0; kk < 32; kk += 4) {
#pragma unroll
                for (int r = 0; r < 4; r++) {
                    ulonglong2 v = *(const ulonglong2*)(ap + (size_t)(rs + r) * 64 + kk);
                    ffma2(acc[0][r], v.x, w[0][kk / 2]);
                    ffma2(acc[0][r], v.y, w[0][kk / 2 + 1]);
                    ffma2(acc[1][r], v.x, w[1][kk / 2]);
                    ffma2(acc[1][r], v.y, w[1][kk / 2 + 1]);
                }
            }
#pragma unroll
            for (int c = 0; c < 2; c++)
#pragma unroll
                for (int r = 0; r < 4; r++)
                    s_gp[(size_t)((c * 2 + glo) * 4 + q) * BT * 64 + (rs + r) * 64 + u]
                        = hsum2(acc[c][r]);
        }
        __syncthreads();  // bar A: partials rows 0-7 ready

        // ---- phase 2: ML rows 8..13 (chunks 4+2)  ||  EW rows 0..7 ----
#pragma unroll
        for (int ch = 0; ch < 2; ch++) {
            const int rs = 8 + ch * 4;
            const int rn = (ch == 0) ? 4 : 2;
            uint64_t acc[2][4];
#pragma unroll
            for (int c = 0; c < 2; c++)
#pragma unroll
                for (int r = 0; r < 4; r++) acc[c][r] = bias[c];
#pragma unroll
            for (int kk = 0; kk < 32; kk += 4) {
#pragma unroll
                for (int r = 0; r < 4; r++) {
                    if (r < rn) {
                        ulonglong2 v = *(const ulonglong2*)(ap + (size_t)(rs + r) * 64 + kk);
                        ffma2(acc[0][r], v.x, w[0][kk / 2]);
                        ffma2(acc[0][r], v.y, w[0][kk / 2 + 1]);
                        ffma2(acc[1][r], v.x, w[1][kk / 2]);
                        ffma2(acc[1][r], v.y, w[1][kk / 2 + 1]);
                    }
                }
            }
#pragma unroll
            for (int c = 0; c < 2; c++)
#pragma unroll
                for (int r = 0; r < 4; r++)
                    if (r < rn)
                        s_gp[(size_t)((c * 2 + glo) * 4 + q) * BT * 64 + (rs + r) * 64 + u]
                            = hsum2(acc[c][r]);
        }
        // EW rows 0..7: one unit per thread (8*64 = 512). Reads s_gp rows 0-7
        // (ready after bar A), writes s_h rows 0-7 (disjoint from ML2's reads).
        {
            const int r  = tid >> 6;
            const int uu = tid & 63;
            float gi = 0.f, gf = 0.f, gg = 0.f, go = 0.f;
#pragma unroll
            for (int qq = 0; qq < 4; qq++) {
                const float* gpb = s_gp + (size_t)qq * BT * 64 + r * 64 + uu;
                gi += gpb[0 * 4 * BT * 64];
                gf += gpb[1 * 4 * BT * 64];
                gg += gpb[2 * 4 * BT * 64];
                go += gpb[3 * 4 * BT * 64];
            }
            float iv = sigm(gi), fv = sigm(gf), gv = tanh_(gg), ov = sigm(go);
            float cc = fmaf(fv, s_c[r * 64 + uu], iv * gv);
            float hh = ov * tanh_(cc);
            s_c[r * 64 + uu] = cc;
            s_h[r * 64 + uu] = hh;
            out[((size_t)t * BP + b0 + r) * 64 + uu] = hh;
        }
        __syncthreads();  // bar B: partials rows 8-13 ready; h rows 0-7 final

        // ---- phase 3: EW rows 8..13 (384 threads)  ||  commit x(t+1) ----
        if (tid < 384) {
            const int r  = 8 + (tid >> 6);
            const int uu = tid & 63;
            float gi = 0.f, gf = 0.f, gg = 0.f, go = 0.f;
#pragma unroll
            for (int qq = 0; qq < 4; qq++) {
                const float* gpb = s_gp + (size_t)qq * BT * 64 + r * 64 + uu;
                gi += gpb[0 * 4 * BT * 64];
                gf += gpb[1 * 4 * BT * 64];
                gg += gpb[2 * 4 * BT * 64];
                go += gpb[3 * 4 * BT * 64];
            }
            float iv = sigm(gi), fv = sigm(gf), gv = tanh_(gg), ov = sigm(go);
            float cc = fmaf(fv, s_c[r * 64 + uu], iv * gv);
            float hh = ov * tanh_(cc);
            s_c[r * 64 + uu] = cc;
            s_h[r * 64 + uu] = hh;
            out[((size_t)t * BP + b0 + r) * 64 + uu] = hh;
        }
        if (do_pf)
            ((float4*)(s_x + nxt * BT * 64))[tid] = pf;
        __syncthreads();  // bar C: h complete, x(t+1) staged
    }
}

// ---------------------------------------------------------------------------
// Output MLP: h[T,BP,64] -> relu(h@wo1^T+bo1)@wo2^T+bo2 -> out[B,T,4]
// ---------------------------------------------------------------------------
__global__ void mlp_out_kernel(int insel,
                               const float* __restrict__ wo1, const float* __restrict__ bo1,
                               const float* __restrict__ wo2, const float* __restrict__ bo2,
                               float* __restrict__ outp)
{
    __shared__ float s_w1[32][64];
    __shared__ float s_b1[32];
    __shared__ float s_w2[4][32];
    __shared__ float s_b2[4];
    int tid = threadIdx.x;
    for (int i = tid; i < 32 * 64; i += 256) s_w1[i / 64][i % 64] = wo1[i];
    if (tid < 32) s_b1[tid] = bo1[tid];
    if (tid < 128) s_w2[tid / 32][tid % 32] = wo2[tid];
    if (tid < 4) s_b2[tid] = bo2[tid];
    __syncthreads();

    const float* in = bufptr(insel);
    int idx = blockIdx.x * blockDim.x + tid;   // idx = t*B + b (coalesced h reads)
    int t = idx / BB;
    int b = idx % BB;

    float h[64];
    const float4* src = reinterpret_cast<const float4*>(in + ((size_t)t * BP + b) * 64);
#pragma unroll
    for (int i = 0; i < 16; i++) {
        float4 v = src[i];
        h[4 * i + 0] = v.x; h[4 * i + 1] = v.y; h[4 * i + 2] = v.z; h[4 * i + 3] = v.w;
    }

    float h2[32];
#pragma unroll
    for (int j = 0; j < 32; j++) {
        float o = s_b1[j];
#pragma unroll
        for (int k = 0; k < 64; k++) o = fmaf(s_w1[j][k], h[k], o);
        h2[j] = fmaxf(o, 0.0f);
    }
    float* dst = outp + ((size_t)b * TT + t) * 4;
#pragma unroll
    for (int j = 0; j < 4; j++) {
        float o = s_b2[j];
#pragma unroll
        for (int k = 0; k < 32; k++) o = fmaf(s_w2[j][k], h2[k], o);
        dst[j] = o;
    }
}

// ---------------------------------------------------------------------------
extern "C" void kernel_launch(void* const* d_in, const int* in_sizes, int n_in,
                              void* d_out, int out_size)
{
    const float* x     = (const float*)d_in[0];
    const float* w1    = (const float*)d_in[1];
    const float* b1    = (const float*)d_in[2];
    const float* w2    = (const float*)d_in[3];
    const float* b2    = (const float*)d_in[4];
    const float* w_ih0 = (const float*)d_in[5];
    const float* w_hh0 = (const float*)d_in[6];
    const float* b_ih0 = (const float*)d_in[7];
    const float* b_hh0 = (const float*)d_in[8];
    const float* w_ih  = (const float*)d_in[9];   // (7, 256, 64)
    const float* w_hh  = (const float*)d_in[10];  // (7, 256, 64)
    const float* b_ih  = (const float*)d_in[11];  // (7, 256)
    const float* b_hh  = (const float*)d_in[12];  // (7, 256)
    const float* wo1   = (const float*)d_in[13];
    const float* bo1   = (const float*)d_in[14];
    const float* wo2   = (const float*)d_in[15];
    const float* bo2   = (const float*)d_in[16];
    float* outp = (float*)d_out;

    const int smem_sz = (2 * BT * 64 + 2 * BT * 64 + 16 * BT * 64) * 4;  // 71680 B
    cudaFuncSetAttribute(lstm_fused<16>, cudaFuncAttributeMaxDynamicSharedMemorySize, smem_sz);
    cudaFuncSetAttribute(lstm_fused<64>, cudaFuncAttributeMaxDynamicSharedMemorySize, smem_sz);

    const int nelem = BB * TT;               // 131072

    mlp_in_kernel<<<nelem / 256, 256>>>(x, w1, b1, w2, b2);

    // layer 0: A -> B (x cols 16-63 are zero; IR=16 weights)
    lstm_fused<16><<<NCTA, 512, smem_sz>>>(0, 1, w_ih0, w_hh0, b_ih0, b_hh0);

    // layers 1..7: ping-pong B->A->B->...
    int cur = 1;
    for (int l = 0; l < NL - 1; l++) {
        int nxt = cur ^ 1;
        lstm_fused<64><<<NCTA, 512, smem_sz>>>(cur, nxt,
                                               w_ih + (size_t)l * GG * HH,
                                               w_hh + (size_t)l * GG * HH,
                                               b_ih + (size_t)l * GG,
                                               b_hh + (size_t)l * GG);
        cur = nxt;
    }

    mlp_out_kernel<<<nelem / 256, 256>>>(cur, wo1, bo1, wo2, bo2, outp);
}